// round 3
// baseline (speedup 1.0000x reference)
#include <cuda_runtime.h>
#include <math_constants.h>

#define NN 100000
#define EE 600000

// ---------------- scratch (device globals: no allocs allowed) ----------------
__device__ float g_q[NN * 128];
__device__ float g_k[NN * 128];
__device__ float g_v[NN * 128];
__device__ float g_e[(size_t)EE * 128];   // per-edge lin_edge output (307 MB)
__device__ float g_alpha[EE * 2];
__device__ float g_ex[EE * 2];
__device__ float g_amax[NN * 2];
__device__ float g_denom[NN * 2];

__device__ __forceinline__ void atomicMaxF(float* addr, float value) {
    if (value >= 0.f)
        atomicMax((int*)addr, __float_as_int(value));
    else
        atomicMin((unsigned int*)addr, (unsigned int)__float_as_int(value));
}

__device__ __forceinline__ void split_tf32(float v, unsigned& hi, unsigned& lo) {
    float h, l;
    asm("cvt.rna.tf32.f32 %0, %1;" : "=f"(h) : "f"(v));
    float rem = v - h;
    asm("cvt.rna.tf32.f32 %0, %1;" : "=f"(l) : "f"(rem));
    hi = __float_as_uint(h);
    lo = __float_as_uint(l);
}

__device__ __forceinline__ void mma8(float* c,
                                     unsigned a0, unsigned a1, unsigned a2, unsigned a3,
                                     unsigned b0, unsigned b1) {
    asm volatile(
        "mma.sync.aligned.m16n8k8.row.col.f32.tf32.tf32.f32 "
        "{%0,%1,%2,%3},{%4,%5,%6,%7},{%8,%9},{%0,%1,%2,%3};"
        : "+f"(c[0]), "+f"(c[1]), "+f"(c[2]), "+f"(c[3])
        : "r"(a0), "r"(a1), "r"(a2), "r"(a3), "r"(b0), "r"(b1));
}

// ---------------- kernel 0: init segment buffers ----------------
__global__ void init_kernel() {
    int i = blockIdx.x * blockDim.x + threadIdx.x;
    if (i < NN * 2) {
        g_amax[i] = -CUDART_INF_F;
        g_denom[i] = 0.f;
    }
}

// ---------------- kernel 1: node projections via 3xTF32 mma ----------------
// grid (ceil(N/128), 4), 256 threads. blockIdx.y picks projection.
// smem: Wt[128][132] transposed + xs[128][132]  = 135168 B
#define NODE_SMEM (2 * 128 * 132 * 4)
__global__ void __launch_bounds__(256, 1)
node_gemm_kernel(const float* __restrict__ x,
                 const float* __restrict__ Wq, const float* __restrict__ bq,
                 const float* __restrict__ Wk, const float* __restrict__ bk,
                 const float* __restrict__ Wv, const float* __restrict__ bv,
                 const float* __restrict__ Wsk, const float* __restrict__ bsk,
                 float* __restrict__ out_skip)
{
    extern __shared__ float sm[];
    float* Wt = sm;              // [n][k], stride 132
    float* xs = sm + 128 * 132;  // [row][k], stride 132

    const int tid = threadIdx.x;
    const float* W; const float* bias; float* dst;
    switch (blockIdx.y) {
        case 0:  W = Wq;  bias = bq;  dst = g_q;      break;
        case 1:  W = Wk;  bias = bk;  dst = g_k;      break;
        case 2:  W = Wv;  bias = bv;  dst = g_v;      break;
        default: W = Wsk; bias = bsk; dst = out_skip; break;
    }

    // load W transposed into smem: Wt[n*132+k] = W[k*128+n]
    #pragma unroll
    for (int i = 0; i < 64; i++) {
        int idx = i * 256 + tid;
        int k = idx >> 7, n = idx & 127;
        Wt[n * 132 + k] = W[idx];
    }
    const int row0 = blockIdx.x * 128;
    #pragma unroll
    for (int i = 0; i < 16; i++) {
        int idx = i * 256 + tid;
        int r = idx >> 5, c4 = idx & 31;
        float4 v = make_float4(0.f, 0.f, 0.f, 0.f);
        if (row0 + r < NN) v = ((const float4*)x)[(row0 + r) * 32 + c4];
        *(float4*)(xs + r * 132 + c4 * 4) = v;
    }
    __syncthreads();

    const int w = tid >> 5, lane = tid & 31;
    const int m0 = (w & 3) * 32;
    const int n0 = (w >> 2) * 64;
    const int qr = lane >> 2, rr = lane & 3;

    float acc[2][8][4];
    #pragma unroll
    for (int mt = 0; mt < 2; mt++)
        #pragma unroll
        for (int nt = 0; nt < 8; nt++)
            #pragma unroll
            for (int j = 0; j < 4; j++) acc[mt][nt][j] = 0.f;

    for (int k0 = 0; k0 < 128; k0 += 8) {
        unsigned ahi[2][4], alo[2][4];
        #pragma unroll
        for (int mt = 0; mt < 2; mt++) {
            const float* base = xs + (m0 + mt * 16 + qr) * 132 + k0 + rr;
            split_tf32(base[0],           ahi[mt][0], alo[mt][0]);
            split_tf32(base[8 * 132],     ahi[mt][1], alo[mt][1]);
            split_tf32(base[4],           ahi[mt][2], alo[mt][2]);
            split_tf32(base[8 * 132 + 4], ahi[mt][3], alo[mt][3]);
        }
        unsigned bhi[8][2], blo[8][2];
        #pragma unroll
        for (int nt = 0; nt < 8; nt++) {
            const float* bb = Wt + (n0 + nt * 8 + qr) * 132 + k0 + rr;
            split_tf32(bb[0], bhi[nt][0], blo[nt][0]);
            split_tf32(bb[4], bhi[nt][1], blo[nt][1]);
        }
        #pragma unroll
        for (int mt = 0; mt < 2; mt++)
            #pragma unroll
            for (int nt = 0; nt < 8; nt++) {
                mma8(acc[mt][nt], ahi[mt][0], ahi[mt][1], ahi[mt][2], ahi[mt][3],
                     bhi[nt][0], bhi[nt][1]);
                mma8(acc[mt][nt], ahi[mt][0], ahi[mt][1], ahi[mt][2], ahi[mt][3],
                     blo[nt][0], blo[nt][1]);
                mma8(acc[mt][nt], alo[mt][0], alo[mt][1], alo[mt][2], alo[mt][3],
                     bhi[nt][0], bhi[nt][1]);
            }
    }

    // epilogue: add bias, store
    #pragma unroll
    for (int mt = 0; mt < 2; mt++) {
        #pragma unroll
        for (int nt = 0; nt < 8; nt++) {
            int col = n0 + nt * 8 + 2 * rr;
            float b0 = __ldg(bias + col);
            float b1 = __ldg(bias + col + 1);
            int r1 = row0 + m0 + mt * 16 + qr;
            if (r1 < NN)
                *(float2*)(dst + (size_t)r1 * 128 + col) =
                    make_float2(acc[mt][nt][0] + b0, acc[mt][nt][1] + b1);
            if (r1 + 8 < NN)
                *(float2*)(dst + (size_t)(r1 + 8) * 128 + col) =
                    make_float2(acc[mt][nt][2] + b0, acc[mt][nt][3] + b1);
        }
    }
}

// ---------------- kernel 2: edge GEMM (3xTF32) + attention logits ----------------
// 128 edges per block, 256 threads.
#define EDGE_SMEM ((3 * 128 * 132 + 128 + 64 + 64 + 128 + 128) * 4)
__global__ void __launch_bounds__(256, 1)
edge_kernel(const float* __restrict__ last_update,
            const int* __restrict__ eidx,
            const float* __restrict__ t,
            const float* __restrict__ msg,
            const float* __restrict__ wt,
            const float* __restrict__ bt,
            const float* __restrict__ We)
{
    extern __shared__ float sm[];
    float* Wt    = sm;                  // [n][k] stride 132
    float* as    = sm + 128 * 132;      // edge_attr tile [row][k] stride 132
    float* es    = as + 128 * 132;      // e tile [row][col] stride 132
    float* relts = es + 128 * 132;      // 128
    float* wts   = relts + 128;         // 64
    float* bts   = wts + 64;            // 64
    int*   srcs  = (int*)(bts + 64);    // 128
    int*   dsts  = srcs + 128;          // 128

    const int tid = threadIdx.x;
    const int e0 = blockIdx.x * 128;

    // phase 1: W transpose load + aux
    #pragma unroll
    for (int i = 0; i < 64; i++) {
        int idx = i * 256 + tid;
        int k = idx >> 7, n = idx & 127;
        Wt[n * 132 + k] = We[idx];
    }
    if (tid < 64) {
        wts[tid] = wt[tid];
        bts[tid] = bt[tid];
    }
    if (tid >= 128) {
        int r = tid - 128;
        int e = e0 + r;
        int s = 0, d = 0; float rt_ = 0.f;
        if (e < EE) {
            s = eidx[e];
            d = eidx[EE + e];
            rt_ = last_update[s] - t[e];
        }
        srcs[r] = s; dsts[r] = d; relts[r] = rt_;
        // second half of rows
        r += 128; // no-op: only 128 rows, handled below
    }
    __syncthreads();
    // rows 0..127 handled by tids 128..255 above covers r=0..127 ✓

    // phase 2: build edge_attr tile (cols 0..63 time-enc, 64..127 msg)
    #pragma unroll
    for (int i = 0; i < 16; i++) {
        int idx = i * 256 + tid;
        int r = idx >> 5, c4 = idx & 31;
        float4 v = make_float4(0.f, 0.f, 0.f, 0.f);
        if (c4 < 16) {
            int c = c4 * 4;
            float rt_ = relts[r];
            v.x = cosf(fmaf(rt_, wts[c + 0], bts[c + 0]));
            v.y = cosf(fmaf(rt_, wts[c + 1], bts[c + 1]));
            v.z = cosf(fmaf(rt_, wts[c + 2], bts[c + 2]));
            v.w = cosf(fmaf(rt_, wts[c + 3], bts[c + 3]));
        } else {
            if (e0 + r < EE)
                v = ((const float4*)msg)[(size_t)(e0 + r) * 16 + (c4 - 16)];
        }
        *(float4*)(as + r * 132 + c4 * 4) = v;
    }
    __syncthreads();

    const int w = tid >> 5, lane = tid & 31;
    const int m0 = (w & 3) * 32;
    const int n0 = (w >> 2) * 64;
    const int qr = lane >> 2, rr = lane & 3;

    float acc[2][8][4];
    #pragma unroll
    for (int mt = 0; mt < 2; mt++)
        #pragma unroll
        for (int nt = 0; nt < 8; nt++)
            #pragma unroll
            for (int j = 0; j < 4; j++) acc[mt][nt][j] = 0.f;

    for (int k0 = 0; k0 < 128; k0 += 8) {
        unsigned ahi[2][4], alo[2][4];
        #pragma unroll
        for (int mt = 0; mt < 2; mt++) {
            const float* base = as + (m0 + mt * 16 + qr) * 132 + k0 + rr;
            split_tf32(base[0],           ahi[mt][0], alo[mt][0]);
            split_tf32(base[8 * 132],     ahi[mt][1], alo[mt][1]);
            split_tf32(base[4],           ahi[mt][2], alo[mt][2]);
            split_tf32(base[8 * 132 + 4], ahi[mt][3], alo[mt][3]);
        }
        unsigned bhi[8][2], blo[8][2];
        #pragma unroll
        for (int nt = 0; nt < 8; nt++) {
            const float* bb = Wt + (n0 + nt * 8 + qr) * 132 + k0 + rr;
            split_tf32(bb[0], bhi[nt][0], blo[nt][0]);
            split_tf32(bb[4], bhi[nt][1], blo[nt][1]);
        }
        #pragma unroll
        for (int mt = 0; mt < 2; mt++)
            #pragma unroll
            for (int nt = 0; nt < 8; nt++) {
                mma8(acc[mt][nt], ahi[mt][0], ahi[mt][1], ahi[mt][2], ahi[mt][3],
                     bhi[nt][0], bhi[nt][1]);
                mma8(acc[mt][nt], ahi[mt][0], ahi[mt][1], ahi[mt][2], ahi[mt][3],
                     blo[nt][0], blo[nt][1]);
                mma8(acc[mt][nt], alo[mt][0], alo[mt][1], alo[mt][2], alo[mt][3],
                     bhi[nt][0], bhi[nt][1]);
            }
    }

    // write accumulators to es tile
    #pragma unroll
    for (int mt = 0; mt < 2; mt++) {
        #pragma unroll
        for (int nt = 0; nt < 8; nt++) {
            int col = n0 + nt * 8 + 2 * rr;
            int r1 = m0 + mt * 16 + qr;
            *(float2*)(es + r1 * 132 + col) =
                make_float2(acc[mt][nt][0], acc[mt][nt][1]);
            *(float2*)(es + (r1 + 8) * 132 + col) =
                make_float2(acc[mt][nt][2], acc[mt][nt][3]);
        }
    }
    __syncthreads();

    // store e tile to gmem (coalesced float4)
    #pragma unroll
    for (int i = 0; i < 16; i++) {
        int idx = i * 256 + tid;
        int r = idx >> 5, c4 = idx & 31;
        if (e0 + r < EE)
            ((float4*)g_e)[(size_t)(e0 + r) * 32 + c4] =
                *(const float4*)(es + r * 132 + c4 * 4);
    }

    // alpha: one thread per (row, head), dot over 64 channels
    {
        int r = tid >> 1;
        int h = tid & 1;
        if (e0 + r < EE) {
            int s = srcs[r], d = dsts[r];
            const float4* qp = (const float4*)(g_q + (size_t)d * 128 + h * 64);
            const float4* kp = (const float4*)(g_k + (size_t)s * 128 + h * 64);
            const float* ep = es + r * 132 + h * 64;
            float acc_ = 0.f;
            #pragma unroll
            for (int c4 = 0; c4 < 16; c4++) {
                float4 qv = qp[c4];
                float4 kv = kp[c4];
                float4 ev = *(const float4*)(ep + c4 * 4);
                acc_ += qv.x * (kv.x + ev.x) + qv.y * (kv.y + ev.y)
                      + qv.z * (kv.z + ev.z) + qv.w * (kv.w + ev.w);
            }
            g_alpha[(size_t)(e0 + r) * 2 + h] = acc_ * 0.125f;  // 1/sqrt(64)
        }
    }
}

// ---------------- kernel 3: segment max ----------------
__global__ void amax_kernel(const int* __restrict__ eidx) {
    int i = blockIdx.x * blockDim.x + threadIdx.x;
    if (i >= EE * 2) return;
    int e = i >> 1;
    int h = i & 1;
    int d = eidx[EE + e];
    atomicMaxF(&g_amax[d * 2 + h], g_alpha[i]);
}

// ---------------- kernel 4: exp + segment sum ----------------
__global__ void ex_kernel(const int* __restrict__ eidx) {
    int i = blockIdx.x * blockDim.x + threadIdx.x;
    if (i >= EE * 2) return;
    int e = i >> 1;
    int h = i & 1;
    int d = eidx[EE + e];
    float ex = expf(g_alpha[i] - g_amax[d * 2 + h]);
    g_ex[i] = ex;
    atomicAdd(&g_denom[d * 2 + h], ex);
}

// ---------------- kernel 5: weighted scatter-add aggregation ----------------
__global__ void agg_kernel(const int* __restrict__ eidx, float* __restrict__ out) {
    long i = (long)blockIdx.x * blockDim.x + threadIdx.x;
    if (i >= (long)EE * 32) return;
    int e  = (int)(i >> 5);
    int c4 = (int)(i & 31);
    int c  = c4 * 4;
    int h  = c4 >> 4;
    int s = eidx[e];
    int d = eidx[EE + e];
    float attn = g_ex[e * 2 + h] / (g_denom[d * 2 + h] + 1e-16f);
    float4 vv = *(const float4*)(g_v + (size_t)s * 128 + c);
    float4 ev = *(const float4*)(g_e + (size_t)e * 128 + c);
    float x0 = attn * (vv.x + ev.x);
    float x1 = attn * (vv.y + ev.y);
    float x2 = attn * (vv.z + ev.z);
    float x3 = attn * (vv.w + ev.w);
    float* p = out + (size_t)d * 128 + c;
    asm volatile("red.global.add.v4.f32 [%0], {%1, %2, %3, %4};"
                 :: "l"(p), "f"(x0), "f"(x1), "f"(x2), "f"(x3) : "memory");
}

// ---------------- launch ----------------
extern "C" void kernel_launch(void* const* d_in, const int* in_sizes, int n_in,
                              void* d_out, int out_size) {
    const float* x    = (const float*)d_in[0];
    const float* lu   = (const float*)d_in[1];
    const int*   eidx = (const int*)d_in[2];
    const float* t    = (const float*)d_in[3];
    const float* msg  = (const float*)d_in[4];
    const float* wt   = (const float*)d_in[5];
    const float* bt   = (const float*)d_in[6];
    const float* Wq   = (const float*)d_in[7];
    const float* bq   = (const float*)d_in[8];
    const float* Wk   = (const float*)d_in[9];
    const float* bk   = (const float*)d_in[10];
    const float* Wv   = (const float*)d_in[11];
    const float* bv   = (const float*)d_in[12];
    const float* We   = (const float*)d_in[13];
    const float* Wsk  = (const float*)d_in[14];
    const float* bsk  = (const float*)d_in[15];
    float* out = (float*)d_out;

    cudaFuncSetAttribute(node_gemm_kernel, cudaFuncAttributeMaxDynamicSharedMemorySize, NODE_SMEM);
    cudaFuncSetAttribute(edge_kernel,      cudaFuncAttributeMaxDynamicSharedMemorySize, EDGE_SMEM);

    init_kernel<<<(NN * 2 + 255) / 256, 256>>>();
    node_gemm_kernel<<<dim3((NN + 127) / 128, 4), 256, NODE_SMEM>>>(
        x, Wq, bq, Wk, bk, Wv, bv, Wsk, bsk, out);
    edge_kernel<<<(EE + 127) / 128, 256, EDGE_SMEM>>>(lu, eidx, t, msg, wt, bt, We);
    amax_kernel<<<(EE * 2 + 255) / 256, 256>>>(eidx);
    ex_kernel<<<(EE * 2 + 255) / 256, 256>>>(eidx);
    agg_kernel<<<(int)(((long)EE * 32 + 255) / 256), 256>>>(eidx, out);
}

// round 7
// speedup vs baseline: 1.4006x; 1.4006x over previous
#include <cuda_runtime.h>
#include <math_constants.h>

#define NN 100000
#define EE 600000

// ---------------- scratch ----------------
__device__ float g_q[NN * 128];
__device__ float g_k[NN * 128];
__device__ float g_v[NN * 128];
__device__ float g_qe[(size_t)NN * 256];    // per-node, per-head We^T q  (102MB)
__device__ float g_ts[(size_t)EE * 64];     // time encoding per edge     (154MB)
__device__ float g_accA[(size_t)NN * 256];  // attn-weighted edge_attr sums
__device__ float g_alpha[EE * 2];
__device__ float g_ex[EE * 2];
__device__ float g_amax[NN * 2];
__device__ float g_denom[NN * 2];

__device__ __forceinline__ void atomicMaxF(float* addr, float value) {
    if (value >= 0.f)
        atomicMax((int*)addr, __float_as_int(value));
    else
        atomicMin((unsigned int*)addr, (unsigned int)__float_as_int(value));
}

__device__ __forceinline__ float dot4(float4 a, float4 b) {
    return a.x * b.x + a.y * b.y + a.z * b.z + a.w * b.w;
}

__device__ __forceinline__ void red4(float* p, float4 v) {
    asm volatile("red.global.add.v4.f32 [%0], {%1, %2, %3, %4};"
                 :: "l"(p), "f"(v.x), "f"(v.y), "f"(v.z), "f"(v.w) : "memory");
}

// accurate cos: manual 2pi range reduction + MUFU
__device__ __forceinline__ float cos_fast(float x) {
    float kq = rintf(x * 0.15915494309189535f);
    float r = fmaf(kq, -6.28318548202514648f, x);   // hi = fp32(2pi) (> 2pi)
    r = fmaf(kq, 1.74845553e-07f, r);               // -(2pi - hi) correction
    return __cosf(r);
}

// ---------------- kernel 0: init ----------------
__global__ void init_kernel() {
    int i = blockIdx.x * blockDim.x + threadIdx.x;
    if (i < NN * 64) ((float4*)g_accA)[i] = make_float4(0.f, 0.f, 0.f, 0.f);
    if (i < NN * 2) {
        g_amax[i] = -CUDART_INF_F;
        g_denom[i] = 0.f;
    }
}

// ---------------- kernel 1: node projections (q,k,v,skip) ----------------
#define NODE_SMEM ((16384 + 64 * 132) * 4)
__global__ void node_gemm_kernel(const float* __restrict__ x,
                                 const float* __restrict__ Wq, const float* __restrict__ bq,
                                 const float* __restrict__ Wk, const float* __restrict__ bk,
                                 const float* __restrict__ Wv, const float* __restrict__ bv,
                                 const float* __restrict__ Wsk, const float* __restrict__ bsk,
                                 float* __restrict__ out_skip)
{
    extern __shared__ float sm[];
    float* Ws = sm;             // 128*128
    float* xs = sm + 16384;     // 64 rows * stride 132

    const int tid = threadIdx.x;
    const float* W; const float* bias; float* dst;
    switch (blockIdx.y) {
        case 0:  W = Wq;  bias = bq;  dst = g_q;      break;
        case 1:  W = Wk;  bias = bk;  dst = g_k;      break;
        case 2:  W = Wv;  bias = bv;  dst = g_v;      break;
        default: W = Wsk; bias = bsk; dst = out_skip; break;
    }

    {
        const float4* W4 = (const float4*)W;
        float4* Ws4 = (float4*)Ws;
        #pragma unroll
        for (int i = 0; i < 16; i++) Ws4[i * 256 + tid] = W4[i * 256 + tid];
    }
    const int row0 = blockIdx.x * 64;
    {
        #pragma unroll
        for (int i = 0; i < 8; i++) {
            int idx = i * 256 + tid;
            int r = idx >> 5;
            int c4 = idx & 31;
            float4 v = make_float4(0.f, 0.f, 0.f, 0.f);
            if (row0 + r < NN) v = ((const float4*)x)[(row0 + r) * 32 + c4];
            *(float4*)(xs + r * 132 + c4 * 4) = v;
        }
    }
    __syncthreads();

    const int tx = tid & 15;
    const int ty = tid >> 4;
    const int c0 = tx * 8;
    const int r0 = ty * 4;

    float acc[4][8];
    #pragma unroll
    for (int i = 0; i < 4; i++)
        #pragma unroll
        for (int j = 0; j < 8; j++) acc[i][j] = 0.f;

    #pragma unroll 4
    for (int k = 0; k < 128; k++) {
        float4 b0 = *(const float4*)(Ws + k * 128 + c0);
        float4 b1 = *(const float4*)(Ws + k * 128 + c0 + 4);
        #pragma unroll
        for (int i = 0; i < 4; i++) {
            float a = xs[(r0 + i) * 132 + k];
            acc[i][0] += a * b0.x; acc[i][1] += a * b0.y;
            acc[i][2] += a * b0.z; acc[i][3] += a * b0.w;
            acc[i][4] += a * b1.x; acc[i][5] += a * b1.y;
            acc[i][6] += a * b1.z; acc[i][7] += a * b1.w;
        }
    }

    float bb[8];
    #pragma unroll
    for (int j = 0; j < 8; j++) bb[j] = __ldg(bias + c0 + j);

    #pragma unroll
    for (int i = 0; i < 4; i++) {
        int r = row0 + r0 + i;
        if (r < NN) {
            float4 o0 = make_float4(acc[i][0] + bb[0], acc[i][1] + bb[1],
                                    acc[i][2] + bb[2], acc[i][3] + bb[3]);
            float4 o1 = make_float4(acc[i][4] + bb[4], acc[i][5] + bb[5],
                                    acc[i][6] + bb[6], acc[i][7] + bb[7]);
            *(float4*)(dst + r * 128 + c0)     = o0;
            *(float4*)(dst + r * 128 + c0 + 4) = o1;
        }
    }
}

// ---------------- kernel 2: qe = We_h^T q   [N,2,128] ----------------
// grid (ceil(N/64), 2), 256 threads. qe[n, h*128+j] = sum_c q[n,h*64+c]*We[j*128+h*64+c]
#define QE_SMEM ((64 * 68 + 64 * 132) * 4)
__global__ void __launch_bounds__(256)
qe_kernel(const float* __restrict__ We)
{
    extern __shared__ float sm[];
    float* As = sm;              // [64 rows][stride 68] (K=64)
    float* Bs = sm + 64 * 68;    // [c=64][stride 132]  Bs[c][j] = We[j*128+h*64+c]

    const int tid = threadIdx.x;
    const int h = blockIdx.y;
    const int row0 = blockIdx.x * 64;

    // load B: 8192 elems; consecutive tid -> consecutive c (coalesced)
    #pragma unroll
    for (int i = 0; i < 32; i++) {
        int idx = i * 256 + tid;
        int j = idx >> 6, c = idx & 63;
        Bs[c * 132 + j] = We[j * 128 + h * 64 + c];
    }
    // load A: q[row, h*64 + c]
    #pragma unroll
    for (int i = 0; i < 4; i++) {
        int idx4 = i * 256 + tid;       // 1024 float4
        int r = idx4 >> 4, c4 = idx4 & 15;
        float4 v = make_float4(0.f, 0.f, 0.f, 0.f);
        if (row0 + r < NN) v = *(const float4*)(g_q + (size_t)(row0 + r) * 128 + h * 64 + c4 * 4);
        *(float4*)(As + r * 68 + c4 * 4) = v;
    }
    __syncthreads();

    const int tx = tid & 15;
    const int ty = tid >> 4;
    const int j0 = tx * 8;
    const int r0 = ty * 4;

    float acc[4][8];
    #pragma unroll
    for (int i = 0; i < 4; i++)
        #pragma unroll
        for (int j = 0; j < 8; j++) acc[i][j] = 0.f;

    #pragma unroll 4
    for (int c = 0; c < 64; c++) {
        float4 b0 = *(const float4*)(Bs + c * 132 + j0);
        float4 b1 = *(const float4*)(Bs + c * 132 + j0 + 4);
        #pragma unroll
        for (int i = 0; i < 4; i++) {
            float a = As[(r0 + i) * 68 + c];
            acc[i][0] += a * b0.x; acc[i][1] += a * b0.y;
            acc[i][2] += a * b0.z; acc[i][3] += a * b0.w;
            acc[i][4] += a * b1.x; acc[i][5] += a * b1.y;
            acc[i][6] += a * b1.z; acc[i][7] += a * b1.w;
        }
    }

    #pragma unroll
    for (int i = 0; i < 4; i++) {
        int r = row0 + r0 + i;
        if (r < NN) {
            float* dst = g_qe + (size_t)r * 256 + h * 128 + j0;
            *(float4*)(dst)     = make_float4(acc[i][0], acc[i][1], acc[i][2], acc[i][3]);
            *(float4*)(dst + 4) = make_float4(acc[i][4], acc[i][5], acc[i][6], acc[i][7]);
        }
    }
}

// ---------------- kernel 3: per-edge time-enc + alpha ----------------
// 32 edges/block, 8 lanes per edge.
__global__ void __launch_bounds__(256)
edge_kernel(const float* __restrict__ last_update,
            const int* __restrict__ eidx,
            const float* __restrict__ t,
            const float* __restrict__ msg,
            const float* __restrict__ wt,
            const float* __restrict__ bt)
{
    __shared__ float sts[32 * 68];
    __shared__ float swt[64], sbt[64];

    const int tid = threadIdx.x;
    if (tid < 64) { swt[tid] = wt[tid]; sbt[tid] = bt[tid]; }
    __syncthreads();

    const int w = tid >> 5, lane = tid & 31;
    const int g = lane >> 3, l = lane & 7;
    const int le = w * 4 + g;
    const int e = blockIdx.x * 32 + le;

    const int s = eidx[e];
    const int d = eidx[EE + e];
    const float rt = last_update[s] - t[e];

    // time encoding (8 channels per lane)
    float tsv[8];
    #pragma unroll
    for (int u = 0; u < 8; u++) {
        int c = l * 8 + u;
        tsv[u] = cos_fast(fmaf(rt, swt[c], sbt[c]));
    }
    float4 t0 = make_float4(tsv[0], tsv[1], tsv[2], tsv[3]);
    float4 t1 = make_float4(tsv[4], tsv[5], tsv[6], tsv[7]);
    *(float4*)(sts + le * 68 + l * 8)     = t0;
    *(float4*)(sts + le * 68 + l * 8 + 4) = t1;
    ((float4*)g_ts)[(size_t)e * 16 + l * 2]     = t0;
    ((float4*)g_ts)[(size_t)e * 16 + l * 2 + 1] = t1;
    __syncwarp();

    const float4* q4 = (const float4*)g_q;
    const float4* k4 = (const float4*)g_k;
    const float4* msg4 = (const float4*)msg;
    const float4* qe4 = (const float4*)g_qe;

    // q.k (lane covers chunks l, l+8 of head0; l+16, l+24 of head1)
    size_t qb = (size_t)d * 32, kb = (size_t)s * 32;
    float ph0 = dot4(q4[qb + l], k4[kb + l]) + dot4(q4[qb + l + 8], k4[kb + l + 8]);
    float ph1 = dot4(q4[qb + l + 16], k4[kb + l + 16]) + dot4(q4[qb + l + 24], k4[kb + l + 24]);

    // edge_attr . qe
    float4 tsA = *(const float4*)(sts + le * 68 + l * 4);
    float4 tsB = *(const float4*)(sts + le * 68 + l * 4 + 32);
    float4 m0 = msg4[(size_t)e * 16 + l];
    float4 m1 = msg4[(size_t)e * 16 + l + 8];
    size_t qeb = (size_t)d * 64;
    ph0 += dot4(qe4[qeb + l], tsA) + dot4(qe4[qeb + l + 8], tsB)
         + dot4(qe4[qeb + l + 16], m0) + dot4(qe4[qeb + l + 24], m1);
    ph1 += dot4(qe4[qeb + 32 + l], tsA) + dot4(qe4[qeb + 32 + l + 8], tsB)
         + dot4(qe4[qeb + 32 + l + 16], m0) + dot4(qe4[qeb + 32 + l + 24], m1);

    #pragma unroll
    for (int o = 4; o; o >>= 1) {
        ph0 += __shfl_xor_sync(0xffffffffu, ph0, o);
        ph1 += __shfl_xor_sync(0xffffffffu, ph1, o);
    }
    if (l == 0)
        *(float2*)(g_alpha + (size_t)e * 2) = make_float2(ph0 * 0.125f, ph1 * 0.125f);
}

// ---------------- kernel 4: segment max ----------------
__global__ void amax_kernel(const int* __restrict__ eidx) {
    int i = blockIdx.x * blockDim.x + threadIdx.x;
    if (i >= EE * 2) return;
    int e = i >> 1;
    int h = i & 1;
    int d = eidx[EE + e];
    atomicMaxF(&g_amax[d * 2 + h], g_alpha[i]);
}

// ---------------- kernel 5: exp + segment sum ----------------
__global__ void ex_kernel(const int* __restrict__ eidx) {
    int i = blockIdx.x * blockDim.x + threadIdx.x;
    if (i >= EE * 2) return;
    int e = i >> 1;
    int h = i & 1;
    int d = eidx[EE + e];
    float ex = expf(g_alpha[i] - g_amax[d * 2 + h]);
    g_ex[i] = ex;
    atomicAdd(&g_denom[d * 2 + h], ex);
}

// ---------------- kernel 6: scatter attn*v -> out, attn*edge_attr -> accA ----------------
__global__ void __launch_bounds__(256)
agg_kernel(const int* __restrict__ eidx, const float* __restrict__ msg,
           float* __restrict__ out)
{
    const int tid = threadIdx.x;
    const int w = tid >> 5, lane = tid & 31;
    const int g = lane >> 3, l = lane & 7;
    const int e = blockIdx.x * 32 + w * 4 + g;

    const int s = eidx[e];
    const int d = eidx[EE + e];
    float2 exv = *(const float2*)(g_ex + (size_t)e * 2);
    float2 dn = *(const float2*)(g_denom + (size_t)d * 2);
    float a0 = exv.x / (dn.x + 1e-16f);
    float a1 = exv.y / (dn.y + 1e-16f);

    const float4* v4 = (const float4*)g_v;
    size_t vb = (size_t)s * 32;
    float* ob = out + (size_t)d * 128;
    {
        float4 va = v4[vb + l], vbc = v4[vb + l + 8];
        float4 vc = v4[vb + l + 16], vd = v4[vb + l + 24];
        red4(ob + l * 4,        make_float4(a0 * va.x, a0 * va.y, a0 * va.z, a0 * va.w));
        red4(ob + (l + 8) * 4,  make_float4(a0 * vbc.x, a0 * vbc.y, a0 * vbc.z, a0 * vbc.w));
        red4(ob + (l + 16) * 4, make_float4(a1 * vc.x, a1 * vc.y, a1 * vc.z, a1 * vc.w));
        red4(ob + (l + 24) * 4, make_float4(a1 * vd.x, a1 * vd.y, a1 * vd.z, a1 * vd.w));
    }

    const float4* ts4 = (const float4*)g_ts;
    const float4* msg4 = (const float4*)msg;
    float4 tsA = ts4[(size_t)e * 16 + l];
    float4 tsB = ts4[(size_t)e * 16 + l + 8];
    float4 m0 = msg4[(size_t)e * 16 + l];
    float4 m1 = msg4[(size_t)e * 16 + l + 8];
    float* A = g_accA + (size_t)d * 256;
    red4(A + l * 4,              make_float4(a0 * tsA.x, a0 * tsA.y, a0 * tsA.z, a0 * tsA.w));
    red4(A + (l + 8) * 4,        make_float4(a0 * tsB.x, a0 * tsB.y, a0 * tsB.z, a0 * tsB.w));
    red4(A + (l + 16) * 4,       make_float4(a0 * m0.x, a0 * m0.y, a0 * m0.z, a0 * m0.w));
    red4(A + (l + 24) * 4,       make_float4(a0 * m1.x, a0 * m1.y, a0 * m1.z, a0 * m1.w));
    red4(A + 128 + l * 4,        make_float4(a1 * tsA.x, a1 * tsA.y, a1 * tsA.z, a1 * tsA.w));
    red4(A + 128 + (l + 8) * 4,  make_float4(a1 * tsB.x, a1 * tsB.y, a1 * tsB.z, a1 * tsB.w));
    red4(A + 128 + (l + 16) * 4, make_float4(a1 * m0.x, a1 * m0.y, a1 * m0.z, a1 * m0.w));
    red4(A + 128 + (l + 24) * 4, make_float4(a1 * m1.x, a1 * m1.y, a1 * m1.z, a1 * m1.w));
}

// ---------------- kernel 7: epilogue  out += accA_h @ We_h ----------------
// grid (ceil(N/64), 2), 256 threads. out[n,h*64+c] += sum_d accA[n,h*128+d]*We[d*128+h*64+c]
#define EPI_SMEM ((64 * 132 + 128 * 68) * 4)
__global__ void __launch_bounds__(256)
epi_kernel(const float* __restrict__ We, float* __restrict__ out)
{
    extern __shared__ float sm[];
    float* As = sm;               // [64 rows][stride 132] K=128
    float* Bs = sm + 64 * 132;    // [d=128][stride 68] c=0..63

    const int tid = threadIdx.x;
    const int h = blockIdx.y;
    const int row0 = blockIdx.x * 64;

    #pragma unroll
    for (int i = 0; i < 32; i++) {
        int idx = i * 256 + tid;
        int dd = idx >> 6, c = idx & 63;
        Bs[dd * 68 + c] = We[dd * 128 + h * 64 + c];
    }
    #pragma unroll
    for (int i = 0; i < 8; i++) {
        int idx4 = i * 256 + tid;   // 2048 float4
        int r = idx4 >> 5, k4 = idx4 & 31;
        float4 v = make_float4(0.f, 0.f, 0.f, 0.f);
        if (row0 + r < NN) v = *(const float4*)(g_accA + (size_t)(row0 + r) * 256 + h * 128 + k4 * 4);
        *(float4*)(As + r * 132 + k4 * 4) = v;
    }
    __syncthreads();

    const int tx = tid & 15;
    const int ty = tid >> 4;
    const int c0 = tx * 4;
    const int r0 = ty * 4;

    float acc[4][4];
    #pragma unroll
    for (int i = 0; i < 4; i++)
        #pragma unroll
        for (int j = 0; j < 4; j++) acc[i][j] = 0.f;

    #pragma unroll 4
    for (int k = 0; k < 128; k++) {
        float4 b = *(const float4*)(Bs + k * 68 + c0);
        #pragma unroll
        for (int i = 0; i < 4; i++) {
            float a = As[(r0 + i) * 132 + k];
            acc[i][0] += a * b.x; acc[i][1] += a * b.y;
            acc[i][2] += a * b.z; acc[i][3] += a * b.w;
        }
    }

    #pragma unroll
    for (int i = 0; i < 4; i++) {
        int r = row0 + r0 + i;
        if (r < NN) {
            float* p = out + (size_t)r * 128 + h * 64 + c0;
            float4 cur = *(float4*)p;
            cur.x += acc[i][0]; cur.y += acc[i][1];
            cur.z += acc[i][2]; cur.w += acc[i][3];
            *(float4*)p = cur;
        }
    }
}

// ---------------- launch ----------------
extern "C" void kernel_launch(void* const* d_in, const int* in_sizes, int n_in,
                              void* d_out, int out_size) {
    const float* x    = (const float*)d_in[0];
    const float* lu   = (const float*)d_in[1];
    const int*   eidx = (const int*)d_in[2];
    const float* t    = (const float*)d_in[3];
    const float* msg  = (const float*)d_in[4];
    const float* wt   = (const float*)d_in[5];
    const float* bt   = (const float*)d_in[6];
    const float* Wq   = (const float*)d_in[7];
    const float* bq   = (const float*)d_in[8];
    const float* Wk   = (const float*)d_in[9];
    const float* bk   = (const float*)d_in[10];
    const float* Wv   = (const float*)d_in[11];
    const float* bv   = (const float*)d_in[12];
    const float* We   = (const float*)d_in[13];
    const float* Wsk  = (const float*)d_in[14];
    const float* bsk  = (const float*)d_in[15];
    float* out = (float*)d_out;

    cudaFuncSetAttribute(node_gemm_kernel, cudaFuncAttributeMaxDynamicSharedMemorySize, NODE_SMEM);
    cudaFuncSetAttribute(qe_kernel,        cudaFuncAttributeMaxDynamicSharedMemorySize, QE_SMEM);
    cudaFuncSetAttribute(epi_kernel,       cudaFuncAttributeMaxDynamicSharedMemorySize, EPI_SMEM);

    init_kernel<<<(NN * 64 + 255) / 256, 256>>>();
    node_gemm_kernel<<<dim3((NN + 63) / 64, 4), 256, NODE_SMEM>>>(
        x, Wq, bq, Wk, bk, Wv, bv, Wsk, bsk, out);
    qe_kernel<<<dim3((NN + 63) / 64, 2), 256, QE_SMEM>>>(We);
    edge_kernel<<<EE / 32, 256>>>(lu, eidx, t, msg, wt, bt);
    amax_kernel<<<(EE * 2 + 255) / 256, 256>>>(eidx);
    ex_kernel<<<(EE * 2 + 255) / 256, 256>>>(eidx);
    agg_kernel<<<EE / 32, 256>>>(eidx, msg, out);
    epi_kernel<<<dim3((NN + 63) / 64, 2), 256, EPI_SMEM>>>(We, out);
}